// round 7
// baseline (speedup 1.0000x reference)
#include <cuda_runtime.h>
#include <cuda_fp16.h>
#include <cstdint>
#include <cstddef>

#define N_NODES 12288
#define F 128
#define BM 32
#define BK 64
#define KSPLIT 3
#define KLEN (N_NODES / KSPLIT)      // 4096
#define KSTAGES (KLEN / BK)          // 64
#define TILES_M (N_NODES / BM)       // 384
#define GRID (TILES_M * KSPLIT)      // 1152
#define THREADS 128

#define A_BYTES (BM * 128)           // 4096 per A plane
#define ST_A2   (2 * A_BYTES)        // 8192: [sign][edge]
#define B_BYTES (128 * 128)          // 16384
#define STAGE_BYTES (ST_A2 + B_BYTES)    // 24576
#define SM_MAIN (2 * STAGE_BYTES)        // 49152 (double buffer)
#define STG_NODE SM_MAIN                 // raw staging: node 8KB
#define STG_EDGE (SM_MAIN + 8192)        // edge 8KB
#define SMEM_TOTAL (SM_MAIN + 16384)     // 65536

// Scratch: 6 partial planes [kslice*2 + (0=sign,1=edge)], fp16 featsT tiles, folded weights
__device__ float g_S[(size_t)2 * KSPLIT * N_NODES * F];
__device__ uint4 g_fB[(size_t)(N_NODES / BK) * B_BYTES / 16];
__device__ float g_c[F];
__device__ float g_Wd[F * F];
__device__ float g_b2[F];

// ---------------------------------------------------------------------------
// helpers
// ---------------------------------------------------------------------------
__device__ __forceinline__ uint32_t smem_u32(const void* p) {
    uint32_t a;
    asm("{ .reg .u64 t; cvta.to.shared.u64 t, %1; cvt.u32.u64 %0, t; }"
        : "=r"(a) : "l"(p));
    return a;
}

__device__ __forceinline__ uint32_t pack_h2(float lo, float hi) {
    __half2 h = __floats2half2_rn(lo, hi);
    return *(uint32_t*)&h;
}

__device__ __forceinline__ float sgnf(float v) {
    return (v > 0.f ? 1.f : 0.f) - (v < 0.f ? 1.f : 0.f);
}

#define SWX(off) ((off) ^ (((off) >> 3) & 0x70))
// staging swizzle: per-thread 64B block, XOR keeps 8-lane phases conflict-free
#define SSTG(t, q) ((uint32_t)(((t) * 64 + (q) * 16) ^ (((t) & 6) << 3)))

#define CP_ASYNC16(dst_u32, src) \
    asm volatile("cp.async.cg.shared.global [%0], [%1], 16;" \
                 :: "r"(dst_u32), "l"(src) : "memory")
#define CP_COMMIT() asm volatile("cp.async.commit_group;" ::: "memory")
#define CP_WAIT0()  asm volatile("cp.async.wait_group 0;" ::: "memory")

#define LDS128F(v, addr) \
    asm volatile("ld.shared.v4.f32 {%0,%1,%2,%3}, [%4];" \
                 : "=f"((v).x), "=f"((v).y), "=f"((v).z), "=f"((v).w) : "r"(addr))

#define LDSM_X4(r0, r1, r2, r3, addr) \
    asm volatile("ldmatrix.sync.aligned.m8n8.x4.shared.b16 {%0,%1,%2,%3}, [%4];" \
                 : "=r"(r0), "=r"(r1), "=r"(r2), "=r"(r3) : "r"(addr))

__device__ __forceinline__ void mma_f16(float* d, const uint32_t* a,
                                        uint32_t b0, uint32_t b1) {
    asm volatile(
        "mma.sync.aligned.m16n8k16.row.col.f32.f16.f16.f32 "
        "{%0,%1,%2,%3}, {%4,%5,%6,%7}, {%8,%9}, {%0,%1,%2,%3};\n"
        : "+f"(d[0]), "+f"(d[1]), "+f"(d[2]), "+f"(d[3])
        : "r"(a[0]), "r"(a[1]), "r"(a[2]), "r"(a[3]), "r"(b0), "r"(b1));
}

// ---------------------------------------------------------------------------
// Tiny prepass kernels
// ---------------------------------------------------------------------------
__global__ void zero_c_kernel() { g_c[threadIdx.x] = 0.f; }

__global__ __launch_bounds__(128)
void colsum_kernel(const float* __restrict__ feats) {
    const int t = threadIdx.x;
    const int r0 = blockIdx.x * 128;
    float s = 0.f;
#pragma unroll 4
    for (int r = 0; r < 128; ++r)
        s += feats[(size_t)(r0 + r) * F + t];
    atomicAdd(&g_c[t], s);
}

__global__ __launch_bounds__(128)
void wtrans_kernel(const float* __restrict__ node_weight,
                   const float* __restrict__ node_bias) {
    const int j = threadIdx.x;
    float b = node_bias[j];
#pragma unroll 4
    for (int k = 0; k < 128; ++k) {
        const float wt = node_weight[(size_t)k * F + j];
        const float wb = node_weight[(size_t)(k + 128) * F + j];
        g_Wd[k * F + j] = 0.5f * (wt - wb);
        b += g_c[k] * 0.5f * (wt + wb);
    }
    g_b2[j] = b;
}

// pre-swizzled fp16 featsT tiles: stage s, (n,k') = feats[s*64+k'][n] at SWX(n*128+k'*2)
__global__ __launch_bounds__(256)
void prep_feats(const float* __restrict__ feats) {
    const int s = blockIdx.x;
    const int t = threadIdx.x;
    const int n = t >> 1;
    const int kh = (t & 1) * 32;
    uint32_t* out = (uint32_t*)g_fB + (size_t)s * (B_BYTES / 4);
    const float* src = feats + (size_t)(s * BK + kh) * F + n;
#pragma unroll
    for (int j = 0; j < 32; j += 2) {
        const float v0 = src[(size_t)j * F];
        const float v1 = src[(size_t)(j + 1) * F];
        const uint32_t off = (uint32_t)(n * 128 + (kh + j) * 2);
        out[SWX(off) >> 2] = pack_h2(v0, v1);
    }
}

// ---------------------------------------------------------------------------
// Main kernel: split-K x3, BM=32, 4 warps (2m x 2n), occ 3.
// Raw adjacency staged via cp.async; converted between stages.
// ---------------------------------------------------------------------------
__global__ __launch_bounds__(THREADS, 3)
void spmm2_f16(const float* __restrict__ node_adj,
               const float* __restrict__ edge_adj) {
    extern __shared__ char smem[];
    const uint32_t sb = smem_u32(smem);
    const int tid  = threadIdx.x;
    const int wid  = tid >> 5;
    const int lane = tid & 31;
    const int M0     = (blockIdx.x % TILES_M) * BM;
    const int kslice = blockIdx.x / TILES_M;
    const size_t K0  = (size_t)kslice * KLEN;

    // ---- converter mapping: thread -> (row r, 16-k group kq) ----
    const int r  = tid >> 2;       // 0..31
    const int kq = tid & 3;        // 0..3
    const float* nrow = node_adj + (size_t)(M0 + r) * N_NODES + K0 + kq * 16;
    const float* erow = edge_adj + (size_t)(M0 + r) * N_NODES + K0 + kq * 16;
    const uint32_t csts0 = SWX((uint32_t)(r * 128 + kq * 32));
    const uint32_t csts1 = SWX((uint32_t)(r * 128 + kq * 32 + 16));
    uint32_t stgN[4], stgE[4];
#pragma unroll
    for (int q = 0; q < 4; ++q) {
        stgN[q] = sb + STG_NODE + SSTG(tid, q);
        stgE[q] = sb + STG_EDGE + SSTG(tid, q);
    }

    // ---- mma mapping: 2m x 2n warps ----
    const int wm = (wid & 1) * 16;
    const int wn = (wid >> 1) * 64;
    const uint32_t arow = wm + (lane & 15);
    const uint32_t abase = arow * 128 + (lane >> 4) * 16;
    const uint32_t axor = (arow & 7) << 4;
    uint32_t bbase[4], bxor[4];
#pragma unroll
    for (int np = 0; np < 4; ++np) {
        const uint32_t brow = wn + np * 16 + ((lane >> 4) << 3) + (lane & 7);
        bbase[np] = brow * 128 + ((lane >> 3) & 1) * 16;
        bxor[np]  = (brow & 7) << 4;
    }

    float acc[2][8][4];
#pragma unroll
    for (int p = 0; p < 2; ++p)
#pragma unroll
        for (int nt = 0; nt < 8; ++nt)
#pragma unroll
            for (int c = 0; c < 4; ++c) acc[p][nt][c] = 0.f;

    const char* fB = (const char*)g_fB + (size_t)(kslice * KSTAGES) * B_BYTES;

    // convert staging -> A tiles of buffer `dbuf`
    auto convert = [&](uint32_t dbuf_off) {
        float4 n0, n1, n2, n3, e0, e1, e2, e3;
        LDS128F(n0, stgN[0]); LDS128F(n1, stgN[1]);
        LDS128F(n2, stgN[2]); LDS128F(n3, stgN[3]);
        LDS128F(e0, stgE[0]); LDS128F(e1, stgE[1]);
        LDS128F(e2, stgE[2]); LDS128F(e3, stgE[3]);
        char* bp = smem + dbuf_off;
        uint4 S0, S1, E0, E1;
        S0 = make_uint4(pack_h2(sgnf(n0.x), sgnf(n0.y)), pack_h2(sgnf(n0.z), sgnf(n0.w)),
                        pack_h2(sgnf(n1.x), sgnf(n1.y)), pack_h2(sgnf(n1.z), sgnf(n1.w)));
        S1 = make_uint4(pack_h2(sgnf(n2.x), sgnf(n2.y)), pack_h2(sgnf(n2.z), sgnf(n2.w)),
                        pack_h2(sgnf(n3.x), sgnf(n3.y)), pack_h2(sgnf(n3.z), sgnf(n3.w)));
        E0 = make_uint4(pack_h2(e0.x, e0.y), pack_h2(e0.z, e0.w),
                        pack_h2(e1.x, e1.y), pack_h2(e1.z, e1.w));
        E1 = make_uint4(pack_h2(e2.x, e2.y), pack_h2(e2.z, e2.w),
                        pack_h2(e3.x, e3.y), pack_h2(e3.z, e3.w));
        *(uint4*)(bp + 0 * A_BYTES + csts0) = S0;
        *(uint4*)(bp + 0 * A_BYTES + csts1) = S1;
        *(uint4*)(bp + 1 * A_BYTES + csts0) = E0;
        *(uint4*)(bp + 1 * A_BYTES + csts1) = E1;
    };
    // issue staging cp.asyncs for stage s (raw adjacency)
    auto stage_adj = [&](int s) {
        const size_t k0 = (size_t)s * BK;
#pragma unroll
        for (int q = 0; q < 4; ++q) {
            CP_ASYNC16(stgN[q], nrow + k0 + q * 4);
            CP_ASYNC16(stgE[q], erow + k0 + q * 4);
        }
    };
    // issue B tile cp.asyncs for stage s into buffer off
    auto stage_B = [&](int s, uint32_t buf_off) {
        const uint32_t dst = sb + buf_off + ST_A2 + tid * 128;
        const char* src = fB + (size_t)s * B_BYTES + tid * 128;
#pragma unroll
        for (int q = 0; q < 8; ++q) CP_ASYNC16(dst + q * 16, src + q * 16);
    };

    // ---- prologue: stage 0 ----
    stage_B(0, 0);
    stage_adj(0);
    CP_COMMIT();
    CP_WAIT0();
    convert(0);
    stage_adj(1);
    CP_COMMIT();
    __syncthreads();

#pragma unroll 1
    for (int s = 0; s < KSTAGES; ++s) {
        const uint32_t cur = (uint32_t)(s & 1) * STAGE_BYTES;
        const uint32_t nxt = (uint32_t)((s + 1) & 1) * STAGE_BYTES;

        // (a) B copy for next stage
        if (s + 1 < KSTAGES) {
            stage_B(s + 1, nxt);
            CP_COMMIT();
        }

        // (b) compute stage s
        const uint32_t sbA = sb + cur;
        const uint32_t sbB = sb + cur + ST_A2;
#pragma unroll
        for (int ks = 0; ks < 4; ++ks) {
            uint32_t b[4][4];
#pragma unroll
            for (int np = 0; np < 4; ++np)
                LDSM_X4(b[np][0], b[np][1], b[np][2], b[np][3],
                        sbB + ((bbase[np] + ks * 32) ^ bxor[np]));
#pragma unroll
            for (int p = 0; p < 2; ++p) {
                uint32_t a[4];
                LDSM_X4(a[0], a[1], a[2], a[3],
                        sbA + p * A_BYTES + ((abase + ks * 32) ^ axor));
#pragma unroll
                for (int np = 0; np < 4; ++np) {
                    mma_f16(acc[p][np * 2],     a, b[np][0], b[np][1]);
                    mma_f16(acc[p][np * 2 + 1], a, b[np][2], b[np][3]);
                }
            }
        }

        // (c) drain copies; convert staging (stage s+1) into nxt; refill staging s+2
        if (s + 1 < KSTAGES) {
            CP_WAIT0();
            convert(nxt);
            if (s + 2 < KSTAGES) {
                stage_adj(s + 2);
                CP_COMMIT();
            }
            __syncthreads();
        }
    }

    // ---- epilogue: write partial planes ----
    const int er0 = wm + (lane >> 2);
    const int ec0 = wn + (lane & 3) * 2;
#pragma unroll
    for (int p = 0; p < 2; ++p) {
        float* base = g_S + ((size_t)(kslice * 2 + p) * N_NODES + M0 + er0) * F + ec0;
#pragma unroll
        for (int nt = 0; nt < 8; ++nt) {
            *(float2*)(base + nt * 8)         = make_float2(acc[p][nt][0], acc[p][nt][1]);
            *(float2*)(base + 8 * F + nt * 8) = make_float2(acc[p][nt][2], acc[p][nt][3]);
        }
    }
}

// ---------------------------------------------------------------------------
// Combine: out = relu(sum_k Ssign_k @ Wd + b2) + sum_k Sedge_k @ We + eb
// ---------------------------------------------------------------------------
#define PLANE_STRIDE ((size_t)2 * N_NODES * F)

__device__ __forceinline__ void accum_block(const float* __restrict__ W,
                                            const float* __restrict__ S,
                                            float* acc,
                                            float* Ws, float* Ss,
                                            int tid, int tx, int ty, int R0) {
#pragma unroll 1
    for (int k0 = 0; k0 < 128; k0 += 32) {
        __syncthreads();
#pragma unroll
        for (int i = 0; i < 4; ++i) {
            const int e = tid + i * 256;
            const int wrow = e >> 5;
            const int wc = (e & 31) * 4;
            *(float4*)(Ws + wrow * 128 + wc) = *(const float4*)(W + (k0 + wrow) * 128 + wc);
        }
        {
            const int srow = tid >> 3;
            const int sc = (tid & 7) * 4;
            const size_t gi = (size_t)(R0 + srow) * F + k0 + sc;
            float4 a0 = *(const float4*)(S + gi);
            float4 a1 = *(const float4*)(S + PLANE_STRIDE + gi);
            float4 a2 = *(const float4*)(S + 2 * PLANE_STRIDE + gi);
            float4 t;
            t.x = a0.x + a1.x + a2.x;  t.y = a0.y + a1.y + a2.y;
            t.z = a0.z + a1.z + a2.z;  t.w = a0.w + a1.w + a2.w;
            *(float4*)(Ss + srow * 36 + sc) = t;
        }
        __syncthreads();
#pragma unroll 8
        for (int kk = 0; kk < 32; ++kk) {
            float w[4], sv[4];
#pragma unroll
            for (int v = 0; v < 4; ++v) w[v] = Ws[kk * 128 + tx + 32 * v];
#pragma unroll
            for (int u = 0; u < 4; ++u) sv[u] = Ss[(ty + 8 * u) * 36 + kk];
#pragma unroll
            for (int u = 0; u < 4; ++u)
#pragma unroll
                for (int v = 0; v < 4; ++v)
                    acc[u * 4 + v] = fmaf(sv[u], w[v], acc[u * 4 + v]);
        }
    }
}

__global__ __launch_bounds__(256)
void combine_kernel(const float* __restrict__ edge_weight,
                    const float* __restrict__ edge_bias,
                    float* __restrict__ out) {
    __shared__ float Ws[32 * 128];
    __shared__ float Ss[32 * 36];

    const int tid = threadIdx.x;
    const int tx = tid & 31;
    const int ty = tid >> 5;
    const int R0 = blockIdx.x * 32;

    float accN[16], accE[16];
#pragma unroll
    for (int i = 0; i < 16; ++i) { accN[i] = 0.f; accE[i] = 0.f; }

    accum_block(g_Wd,        g_S,                        accN, Ws, Ss, tid, tx, ty, R0);
    accum_block(edge_weight, g_S + (size_t)N_NODES * F,  accE, Ws, Ss, tid, tx, ty, R0);

    float b2[4], eb[4];
#pragma unroll
    for (int v = 0; v < 4; ++v) {
        b2[v] = g_b2[tx + 32 * v];
        eb[v] = edge_bias[tx + 32 * v];
    }
#pragma unroll
    for (int u = 0; u < 4; ++u)
#pragma unroll
        for (int v = 0; v < 4; ++v) {
            const int rr = R0 + ty + 8 * u;
            const int c = tx + 32 * v;
            out[(size_t)rr * F + c] =
                fmaxf(accN[u * 4 + v] + b2[v], 0.f) + accE[u * 4 + v] + eb[v];
        }
}

extern "C" void kernel_launch(void* const* d_in, const int* in_sizes, int n_in,
                              void* d_out, int out_size) {
    const float* feats       = (const float*)d_in[0];
    const float* node_adj    = (const float*)d_in[1];
    const float* edge_adj    = (const float*)d_in[2];
    const float* node_weight = (const float*)d_in[3];
    const float* node_bias   = (const float*)d_in[4];
    const float* edge_weight = (const float*)d_in[5];
    const float* edge_bias   = (const float*)d_in[6];
    float* out = (float*)d_out;

    cudaFuncSetAttribute(spmm2_f16, cudaFuncAttributeMaxDynamicSharedMemorySize, SMEM_TOTAL);

    zero_c_kernel<<<1, 128>>>();
    colsum_kernel<<<96, 128>>>(feats);
    wtrans_kernel<<<1, 128>>>(node_weight, node_bias);
    prep_feats<<<N_NODES / BK, 256>>>(feats);
    spmm2_f16<<<GRID, THREADS, SMEM_TOTAL>>>(node_adj, edge_adj);
    combine_kernel<<<N_NODES / 32, 256>>>(edge_weight, edge_bias, out);
}

// round 8
// speedup vs baseline: 1.1286x; 1.1286x over previous
#include <cuda_runtime.h>
#include <cuda_fp16.h>
#include <cstdint>
#include <cstddef>

#define N_NODES 12288
#define F 128
#define BM 96
#define BK 64
#define STAGES (N_NODES / BK)      // 192
#define THREADS 384
#define GRID (N_NODES / BM)        // 128

#define A_BYTES (BM * 128)         // 12288 per A plane (96 rows x 128B)
#define ST_A2   (2 * A_BYTES)      // 24576: [sign][edge]
#define B_BYTES (128 * 128)        // 16384: featsT tile 128n x 64k fp16
#define STAGE_BYTES (ST_A2 + B_BYTES)   // 40960
#define SMEM_TOTAL  (2 * STAGE_BYTES)   // 81920

// Scratch
__device__ float g_S[(size_t)2 * N_NODES * F];        // [sign@f][edge@f]
__device__ uint4 g_fB[(size_t)STAGES * B_BYTES / 16]; // pre-swizzled fp16 featsT
__device__ float g_c[F];
__device__ float g_Wd[F * F];                         // (Wtop - Wbot)/2
__device__ float g_b2[F];                             // c@(Wtop+Wbot)/2 + nb

// ---------------------------------------------------------------------------
// helpers
// ---------------------------------------------------------------------------
__device__ __forceinline__ uint32_t smem_u32(const void* p) {
    uint32_t a;
    asm("{ .reg .u64 t; cvta.to.shared.u64 t, %1; cvt.u32.u64 %0, t; }"
        : "=r"(a) : "l"(p));
    return a;
}

__device__ __forceinline__ uint32_t pack_h2(float lo, float hi) {
    __half2 h = __floats2half2_rn(lo, hi);
    return *(uint32_t*)&h;
}

__device__ __forceinline__ float sgnf(float v) {
    return (v > 0.f ? 1.f : 0.f) - (v < 0.f ? 1.f : 0.f);
}

#define SWX(off) ((off) ^ (((off) >> 3) & 0x70))

#define CP_ASYNC16(dst_u32, src) \
    asm volatile("cp.async.cg.shared.global [%0], [%1], 16;" \
                 :: "r"(dst_u32), "l"(src) : "memory")
#define CP_COMMIT() asm volatile("cp.async.commit_group;" ::: "memory")
#define CP_WAIT0()  asm volatile("cp.async.wait_group 0;" ::: "memory")

#define LDSM_X4(r0, r1, r2, r3, addr) \
    asm volatile("ldmatrix.sync.aligned.m8n8.x4.shared.b16 {%0,%1,%2,%3}, [%4];" \
                 : "=r"(r0), "=r"(r1), "=r"(r2), "=r"(r3) : "r"(addr))

__device__ __forceinline__ void mma_f16(float* d, const uint32_t* a,
                                        uint32_t b0, uint32_t b1) {
    asm volatile(
        "mma.sync.aligned.m16n8k16.row.col.f32.f16.f16.f32 "
        "{%0,%1,%2,%3}, {%4,%5,%6,%7}, {%8,%9}, {%0,%1,%2,%3};\n"
        : "+f"(d[0]), "+f"(d[1]), "+f"(d[2]), "+f"(d[3])
        : "r"(a[0]), "r"(a[1]), "r"(a[2]), "r"(a[3]), "r"(b0), "r"(b1));
}

// ---------------------------------------------------------------------------
// Tiny prepass kernels
// ---------------------------------------------------------------------------
__global__ void zero_c_kernel() { g_c[threadIdx.x] = 0.f; }

__global__ __launch_bounds__(128)
void colsum_kernel(const float* __restrict__ feats) {
    const int t = threadIdx.x;
    const int r0 = blockIdx.x * 128;
    float s = 0.f;
#pragma unroll 4
    for (int r = 0; r < 128; ++r)
        s += feats[(size_t)(r0 + r) * F + t];
    atomicAdd(&g_c[t], s);
}

__global__ __launch_bounds__(128)
void wtrans_kernel(const float* __restrict__ node_weight,
                   const float* __restrict__ node_bias) {
    const int j = threadIdx.x;
    float b = node_bias[j];
#pragma unroll 4
    for (int k = 0; k < 128; ++k) {
        const float wt = node_weight[(size_t)k * F + j];
        const float wb = node_weight[(size_t)(k + 128) * F + j];
        g_Wd[k * F + j] = 0.5f * (wt - wb);
        b += g_c[k] * 0.5f * (wt + wb);
    }
    g_b2[j] = b;
}

// pre-swizzled fp16 featsT tiles: stage s, (n,k') = feats[s*64+k'][n] at SWX(n*128+k'*2)
__global__ __launch_bounds__(256)
void prep_feats(const float* __restrict__ feats) {
    const int s = blockIdx.x;
    const int t = threadIdx.x;
    const int n = t >> 1;
    const int kh = (t & 1) * 32;
    uint32_t* out = (uint32_t*)g_fB + (size_t)s * (B_BYTES / 4);
    const float* src = feats + (size_t)(s * BK + kh) * F + n;
#pragma unroll
    for (int j = 0; j < 32; j += 2) {
        const float v0 = src[(size_t)j * F];
        const float v1 = src[(size_t)(j + 1) * F];
        const uint32_t off = (uint32_t)(n * 128 + (kh + j) * 2);
        out[SWX(off) >> 2] = pack_h2(v0, v1);
    }
}

// ---------------------------------------------------------------------------
// Main kernel: S_sign = sign(node_adj)@feats, S_edge = edge_adj@feats.
// BM=96 rows/CTA, 12 warps (6m x 2n), 1 CTA/SM (grid 128) -> B fill amortized
// over 2x more rows than R6. Register-prefetch adjacency, double-buffer smem.
// ---------------------------------------------------------------------------
__global__ __launch_bounds__(THREADS, 1)
void spmm2_f16(const float* __restrict__ node_adj,
               const float* __restrict__ edge_adj) {
    extern __shared__ char smem[];
    const uint32_t sb = smem_u32(smem);
    const int tid  = threadIdx.x;
    const int wid  = tid >> 5;
    const int lane = tid & 31;
    const int M0   = blockIdx.x * BM;

    // ---- converter mapping: thread -> (row cm, 16-k group kq) ----
    const int cm = tid >> 2;       // 0..95
    const int kq = tid & 3;        // 0..3
    const float* nrow = node_adj + (size_t)(M0 + cm) * N_NODES + kq * 16;
    const float* erow = edge_adj + (size_t)(M0 + cm) * N_NODES + kq * 16;
    const uint32_t csts0 = SWX((uint32_t)(cm * 128 + kq * 32));
    const uint32_t csts1 = SWX((uint32_t)(cm * 128 + kq * 32 + 16));

    // ---- mma mapping: 6m x 2n warps ----
    const int wm = (wid % 6) * 16;
    const int wn = (wid / 6) * 64;
    const uint32_t arow = wm + (lane & 15);
    const uint32_t abase = arow * 128 + (lane >> 4) * 16;
    const uint32_t axor = (arow & 7) << 4;
    uint32_t bbase[4], bxor[4];
#pragma unroll
    for (int np = 0; np < 4; ++np) {
        const uint32_t brow = wn + np * 16 + ((lane >> 4) << 3) + (lane & 7);
        bbase[np] = brow * 128 + ((lane >> 3) & 1) * 16;
        bxor[np]  = (brow & 7) << 4;
    }

    float acc[2][8][4];
#pragma unroll
    for (int p = 0; p < 2; ++p)
#pragma unroll
        for (int nt = 0; nt < 8; ++nt)
#pragma unroll
            for (int c = 0; c < 4; ++c) acc[p][nt][c] = 0.f;

    const char* fB = (const char*)g_fB;

    // ---- prologue: fill buffer 0 (stage 0) ----
    if (tid < 256) {
        const uint32_t dst = sb + ST_A2 + tid * 64;
        const char* src = fB + tid * 64;
#pragma unroll
        for (int q = 0; q < 4; ++q) CP_ASYNC16(dst + q * 16, src + q * 16);
    }
    CP_COMMIT();
    {
        float4 n0 = *(const float4*)(nrow);
        float4 n1 = *(const float4*)(nrow + 4);
        float4 n2 = *(const float4*)(nrow + 8);
        float4 n3 = *(const float4*)(nrow + 12);
        float4 e0 = *(const float4*)(erow);
        float4 e1 = *(const float4*)(erow + 4);
        float4 e2 = *(const float4*)(erow + 8);
        float4 e3 = *(const float4*)(erow + 12);
        uint4 S0, S1, E0, E1;
        S0 = make_uint4(pack_h2(sgnf(n0.x), sgnf(n0.y)), pack_h2(sgnf(n0.z), sgnf(n0.w)),
                        pack_h2(sgnf(n1.x), sgnf(n1.y)), pack_h2(sgnf(n1.z), sgnf(n1.w)));
        S1 = make_uint4(pack_h2(sgnf(n2.x), sgnf(n2.y)), pack_h2(sgnf(n2.z), sgnf(n2.w)),
                        pack_h2(sgnf(n3.x), sgnf(n3.y)), pack_h2(sgnf(n3.z), sgnf(n3.w)));
        E0 = make_uint4(pack_h2(e0.x, e0.y), pack_h2(e0.z, e0.w),
                        pack_h2(e1.x, e1.y), pack_h2(e1.z, e1.w));
        E1 = make_uint4(pack_h2(e2.x, e2.y), pack_h2(e2.z, e2.w),
                        pack_h2(e3.x, e3.y), pack_h2(e3.z, e3.w));
        *(uint4*)(smem + 0 * A_BYTES + csts0) = S0;
        *(uint4*)(smem + 0 * A_BYTES + csts1) = S1;
        *(uint4*)(smem + 1 * A_BYTES + csts0) = E0;
        *(uint4*)(smem + 1 * A_BYTES + csts1) = E1;
    }
    CP_WAIT0();
    __syncthreads();

    float4 nv[4], ev[4];

#pragma unroll 1
    for (int s = 0; s < STAGES; ++s) {
        const uint32_t cur = (uint32_t)(s & 1) * STAGE_BYTES;
        const uint32_t nxt = (uint32_t)((s + 1) & 1) * STAGE_BYTES;

        // (a) prefetch stage s+1: B via cp.async, adjacency via LDG regs
        if (s + 1 < STAGES) {
            if (tid < 256) {
                const uint32_t dst = sb + nxt + ST_A2 + tid * 64;
                const char* src = fB + (size_t)(s + 1) * B_BYTES + tid * 64;
#pragma unroll
                for (int q = 0; q < 4; ++q) CP_ASYNC16(dst + q * 16, src + q * 16);
            }
            CP_COMMIT();
            const size_t k0 = (size_t)(s + 1) * BK;
#pragma unroll
            for (int i = 0; i < 4; ++i) {
                nv[i] = *(const float4*)(nrow + k0 + i * 4);
                ev[i] = *(const float4*)(erow + k0 + i * 4);
            }
        }

        // (b) compute stage s
        const uint32_t sbA = sb + cur;
        const uint32_t sbB = sb + cur + ST_A2;
#pragma unroll
        for (int ks = 0; ks < 4; ++ks) {
            uint32_t b[4][4];
#pragma unroll
            for (int np = 0; np < 4; ++np)
                LDSM_X4(b[np][0], b[np][1], b[np][2], b[np][3],
                        sbB + ((bbase[np] + ks * 32) ^ bxor[np]));
#pragma unroll
            for (int p = 0; p < 2; ++p) {
                uint32_t a[4];
                LDSM_X4(a[0], a[1], a[2], a[3],
                        sbA + p * A_BYTES + ((abase + ks * 32) ^ axor));
#pragma unroll
                for (int np = 0; np < 4; ++np) {
                    mma_f16(acc[p][np * 2],     a, b[np][0], b[np][1]);
                    mma_f16(acc[p][np * 2 + 1], a, b[np][2], b[np][3]);
                }
            }
        }

        // (c) convert + store stage s+1 A tiles; drain B copy; barrier
        if (s + 1 < STAGES) {
            char* bp = smem + ((s + 1) & 1) * STAGE_BYTES;
            uint4 S0, S1, E0, E1;
            S0 = make_uint4(pack_h2(sgnf(nv[0].x), sgnf(nv[0].y)), pack_h2(sgnf(nv[0].z), sgnf(nv[0].w)),
                            pack_h2(sgnf(nv[1].x), sgnf(nv[1].y)), pack_h2(sgnf(nv[1].z), sgnf(nv[1].w)));
            S1 = make_uint4(pack_h2(sgnf(nv[2].x), sgnf(nv[2].y)), pack_h2(sgnf(nv[2].z), sgnf(nv[2].w)),
                            pack_h2(sgnf(nv[3].x), sgnf(nv[3].y)), pack_h2(sgnf(nv[3].z), sgnf(nv[3].w)));
            E0 = make_uint4(pack_h2(ev[0].x, ev[0].y), pack_h2(ev[0].z, ev[0].w),
                            pack_h2(ev[1].x, ev[1].y), pack_h2(ev[1].z, ev[1].w));
            E1 = make_uint4(pack_h2(ev[2].x, ev[2].y), pack_h2(ev[2].z, ev[2].w),
                            pack_h2(ev[3].x, ev[3].y), pack_h2(ev[3].z, ev[3].w));
            *(uint4*)(bp + 0 * A_BYTES + csts0) = S0;
            *(uint4*)(bp + 0 * A_BYTES + csts1) = S1;
            *(uint4*)(bp + 1 * A_BYTES + csts0) = E0;
            *(uint4*)(bp + 1 * A_BYTES + csts1) = E1;
            CP_WAIT0();
            __syncthreads();
        }
    }

    // ---- epilogue: acc -> g_S (fp32) ----
    const int er0 = wm + (lane >> 2);
    const int ec0 = wn + (lane & 3) * 2;
#pragma unroll
    for (int p = 0; p < 2; ++p) {
        float* base = g_S + ((size_t)p * N_NODES + M0 + er0) * F + ec0;
#pragma unroll
        for (int nt = 0; nt < 8; ++nt) {
            *(float2*)(base + nt * 8)         = make_float2(acc[p][nt][0], acc[p][nt][1]);
            *(float2*)(base + 8 * F + nt * 8) = make_float2(acc[p][nt][2], acc[p][nt][3]);
        }
    }
}

// ---------------------------------------------------------------------------
// Combine: out = relu(S_sign@Wd + b2) + S_edge@We + eb
// ---------------------------------------------------------------------------
__device__ __forceinline__ void accum_block(const float* __restrict__ W,
                                            const float* __restrict__ S,
                                            float* acc,
                                            float* Ws, float* Ss,
                                            int tid, int tx, int ty, int R0) {
#pragma unroll 1
    for (int k0 = 0; k0 < 128; k0 += 32) {
        __syncthreads();
#pragma unroll
        for (int i = 0; i < 4; ++i) {
            const int e = tid + i * 256;
            const int wrow = e >> 5;
            const int wc = (e & 31) * 4;
            *(float4*)(Ws + wrow * 128 + wc) = *(const float4*)(W + (k0 + wrow) * 128 + wc);
        }
        {
            const int srow = tid >> 3;
            const int sc = (tid & 7) * 4;
            *(float4*)(Ss + srow * 36 + sc) =
                *(const float4*)(S + (size_t)(R0 + srow) * F + k0 + sc);
        }
        __syncthreads();
#pragma unroll 8
        for (int kk = 0; kk < 32; ++kk) {
            float w[4], sv[4];
#pragma unroll
            for (int v = 0; v < 4; ++v) w[v] = Ws[kk * 128 + tx + 32 * v];
#pragma unroll
            for (int u = 0; u < 4; ++u) sv[u] = Ss[(ty + 8 * u) * 36 + kk];
#pragma unroll
            for (int u = 0; u < 4; ++u)
#pragma unroll
                for (int v = 0; v < 4; ++v)
                    acc[u * 4 + v] = fmaf(sv[u], w[v], acc[u * 4 + v]);
        }
    }
}

__global__ __launch_bounds__(256)
void combine_kernel(const float* __restrict__ edge_weight,
                    const float* __restrict__ edge_bias,
                    float* __restrict__ out) {
    __shared__ float Ws[32 * 128];
    __shared__ float Ss[32 * 36];

    const int tid = threadIdx.x;
    const int tx = tid & 31;
    const int ty = tid >> 5;
    const int R0 = blockIdx.x * 32;

    float accN[16], accE[16];
#pragma unroll
    for (int i = 0; i < 16; ++i) { accN[i] = 0.f; accE[i] = 0.f; }

    accum_block(g_Wd,        g_S,                        accN, Ws, Ss, tid, tx, ty, R0);
    accum_block(edge_weight, g_S + (size_t)N_NODES * F,  accE, Ws, Ss, tid, tx, ty, R0);

    float b2[4], eb[4];
#pragma unroll
    for (int v = 0; v < 4; ++v) {
        b2[v] = g_b2[tx + 32 * v];
        eb[v] = edge_bias[tx + 32 * v];
    }
#pragma unroll
    for (int u = 0; u < 4; ++u)
#pragma unroll
        for (int v = 0; v < 4; ++v) {
            const int rr = R0 + ty + 8 * u;
            const int c = tx + 32 * v;
            out[(size_t)rr * F + c] =
                fmaxf(accN[u * 4 + v] + b2[v], 0.f) + accE[u * 4 + v] + eb[v];
        }
}

extern "C" void kernel_launch(void* const* d_in, const int* in_sizes, int n_in,
                              void* d_out, int out_size) {
    const float* feats       = (const float*)d_in[0];
    const float* node_adj    = (const float*)d_in[1];
    const float* edge_adj    = (const float*)d_in[2];
    const float* node_weight = (const float*)d_in[3];
    const float* node_bias   = (const float*)d_in[4];
    const float* edge_weight = (const float*)d_in[5];
    const float* edge_bias   = (const float*)d_in[6];
    float* out = (float*)d_out;

    cudaFuncSetAttribute(spmm2_f16, cudaFuncAttributeMaxDynamicSharedMemorySize, SMEM_TOTAL);

    zero_c_kernel<<<1, 128>>>();
    colsum_kernel<<<96, 128>>>(feats);
    wtrans_kernel<<<1, 128>>>(node_weight, node_bias);
    prep_feats<<<STAGES, 256>>>(feats);
    spmm2_f16<<<GRID, THREADS, SMEM_TOTAL>>>(node_adj, edge_adj);
    combine_kernel<<<N_NODES / 32, 256>>>(edge_weight, edge_bias, out);
}

// round 9
// speedup vs baseline: 1.2138x; 1.0754x over previous
#include <cuda_runtime.h>
#include <cuda_fp16.h>
#include <cstdint>
#include <cstddef>

#define N_NODES 12288
#define F 128
#define BM 96
#define BK 64
#define KSPLIT 8
#define KLEN (N_NODES / KSPLIT)     // 1536
#define KSTAGES (KLEN / BK)         // 24
#define TILES_M (N_NODES / BM)      // 128
#define GRID (TILES_M * KSPLIT)     // 1024
#define THREADS 384

#define A_BYTES (BM * 128)          // 12288 per A plane
#define ST_A2   (2 * A_BYTES)       // 24576: [sign][edge]
#define B_BYTES (128 * 128)         // 16384
#define STAGE_BYTES (ST_A2 + B_BYTES)   // 40960
#define SMEM_TOTAL  (2 * STAGE_BYTES)   // 81920

#define PLANE ((size_t)N_NODES * F)     // one plane
#define SLICE (2 * PLANE)               // one k-slice (sign+edge)

// Scratch: 8 k-slices x [sign, edge] partial planes (fp32), fp16 featsT tiles, folded W
__device__ float g_S[(size_t)KSPLIT * 2 * N_NODES * F];   // ~101 MB
__device__ uint4 g_fB[(size_t)(N_NODES / BK) * B_BYTES / 16];
__device__ float g_c[F];
__device__ float g_Wd[F * F];
__device__ float g_b2[F];

// ---------------------------------------------------------------------------
// helpers
// ---------------------------------------------------------------------------
__device__ __forceinline__ uint32_t smem_u32(const void* p) {
    uint32_t a;
    asm("{ .reg .u64 t; cvta.to.shared.u64 t, %1; cvt.u32.u64 %0, t; }"
        : "=r"(a) : "l"(p));
    return a;
}

__device__ __forceinline__ uint32_t pack_h2(float lo, float hi) {
    __half2 h = __floats2half2_rn(lo, hi);
    return *(uint32_t*)&h;
}

__device__ __forceinline__ float sgnf(float v) {
    return (v > 0.f ? 1.f : 0.f) - (v < 0.f ? 1.f : 0.f);
}

#define SWX(off) ((off) ^ (((off) >> 3) & 0x70))

#define CP_ASYNC16(dst_u32, src) \
    asm volatile("cp.async.cg.shared.global [%0], [%1], 16;" \
                 :: "r"(dst_u32), "l"(src) : "memory")
#define CP_COMMIT() asm volatile("cp.async.commit_group;" ::: "memory")
#define CP_WAIT0()  asm volatile("cp.async.wait_group 0;" ::: "memory")

#define LDSM_X4(r0, r1, r2, r3, addr) \
    asm volatile("ldmatrix.sync.aligned.m8n8.x4.shared.b16 {%0,%1,%2,%3}, [%4];" \
                 : "=r"(r0), "=r"(r1), "=r"(r2), "=r"(r3) : "r"(addr))

__device__ __forceinline__ void mma_f16(float* d, const uint32_t* a,
                                        uint32_t b0, uint32_t b1) {
    asm volatile(
        "mma.sync.aligned.m16n8k16.row.col.f32.f16.f16.f32 "
        "{%0,%1,%2,%3}, {%4,%5,%6,%7}, {%8,%9}, {%0,%1,%2,%3};\n"
        : "+f"(d[0]), "+f"(d[1]), "+f"(d[2]), "+f"(d[3])
        : "r"(a[0]), "r"(a[1]), "r"(a[2]), "r"(a[3]), "r"(b0), "r"(b1));
}

// ---------------------------------------------------------------------------
// Tiny prepass kernels
// ---------------------------------------------------------------------------
__global__ void zero_c_kernel() { g_c[threadIdx.x] = 0.f; }

__global__ __launch_bounds__(128)
void colsum_kernel(const float* __restrict__ feats) {
    const int t = threadIdx.x;
    const int r0 = blockIdx.x * 128;
    float s = 0.f;
#pragma unroll 4
    for (int r = 0; r < 128; ++r)
        s += feats[(size_t)(r0 + r) * F + t];
    atomicAdd(&g_c[t], s);
}

__global__ __launch_bounds__(128)
void wtrans_kernel(const float* __restrict__ node_weight,
                   const float* __restrict__ node_bias) {
    const int j = threadIdx.x;
    float b = node_bias[j];
#pragma unroll 4
    for (int k = 0; k < 128; ++k) {
        const float wt = node_weight[(size_t)k * F + j];
        const float wb = node_weight[(size_t)(k + 128) * F + j];
        g_Wd[k * F + j] = 0.5f * (wt - wb);
        b += g_c[k] * 0.5f * (wt + wb);
    }
    g_b2[j] = b;
}

// pre-swizzled fp16 featsT tiles: stage s, (n,k') = feats[s*64+k'][n] at SWX(n*128+k'*2)
__global__ __launch_bounds__(256)
void prep_feats(const float* __restrict__ feats) {
    const int s = blockIdx.x;
    const int t = threadIdx.x;
    const int n = t >> 1;
    const int kh = (t & 1) * 32;
    uint32_t* out = (uint32_t*)g_fB + (size_t)s * (B_BYTES / 4);
    const float* src = feats + (size_t)(s * BK + kh) * F + n;
#pragma unroll
    for (int j = 0; j < 32; j += 2) {
        const float v0 = src[(size_t)j * F];
        const float v1 = src[(size_t)(j + 1) * F];
        const uint32_t off = (uint32_t)(n * 128 + (kh + j) * 2);
        out[SWX(off) >> 2] = pack_h2(v0, v1);
    }
}

// ---------------------------------------------------------------------------
// Main kernel: split-K x8. BM=96 rows/CTA over K-slice of 1536.
// 12 warps (6m x 2n), 1 CTA/SM resident, register-prefetch adjacency.
// ---------------------------------------------------------------------------
__global__ __launch_bounds__(THREADS, 1)
void spmm2_f16(const float* __restrict__ node_adj,
               const float* __restrict__ edge_adj) {
    extern __shared__ char smem[];
    const uint32_t sb = smem_u32(smem);
    const int tid  = threadIdx.x;
    const int wid  = tid >> 5;
    const int lane = tid & 31;
    const int M0     = (blockIdx.x % TILES_M) * BM;
    const int kslice = blockIdx.x / TILES_M;
    const size_t K0  = (size_t)kslice * KLEN;

    // ---- converter mapping: thread -> (row cm, 16-k group kq) ----
    const int cm = tid >> 2;       // 0..95
    const int kq = tid & 3;        // 0..3
    const float* nrow = node_adj + (size_t)(M0 + cm) * N_NODES + K0 + kq * 16;
    const float* erow = edge_adj + (size_t)(M0 + cm) * N_NODES + K0 + kq * 16;
    const uint32_t csts0 = SWX((uint32_t)(cm * 128 + kq * 32));
    const uint32_t csts1 = SWX((uint32_t)(cm * 128 + kq * 32 + 16));

    // ---- mma mapping: 6m x 2n warps ----
    const int wm = (wid % 6) * 16;
    const int wn = (wid / 6) * 64;
    const uint32_t arow = wm + (lane & 15);
    const uint32_t abase = arow * 128 + (lane >> 4) * 16;
    const uint32_t axor = (arow & 7) << 4;
    uint32_t bbase[4], bxor[4];
#pragma unroll
    for (int np = 0; np < 4; ++np) {
        const uint32_t brow = wn + np * 16 + ((lane >> 4) << 3) + (lane & 7);
        bbase[np] = brow * 128 + ((lane >> 3) & 1) * 16;
        bxor[np]  = (brow & 7) << 4;
    }

    float acc[2][8][4];
#pragma unroll
    for (int p = 0; p < 2; ++p)
#pragma unroll
        for (int nt = 0; nt < 8; ++nt)
#pragma unroll
            for (int c = 0; c < 4; ++c) acc[p][nt][c] = 0.f;

    const char* fB = (const char*)g_fB + (size_t)(kslice * KSTAGES) * B_BYTES;

    // ---- prologue: fill buffer 0 (stage 0) ----
    if (tid < 256) {
        const uint32_t dst = sb + ST_A2 + tid * 64;
        const char* src = fB + tid * 64;
#pragma unroll
        for (int q = 0; q < 4; ++q) CP_ASYNC16(dst + q * 16, src + q * 16);
    }
    CP_COMMIT();
    {
        float4 n0 = *(const float4*)(nrow);
        float4 n1 = *(const float4*)(nrow + 4);
        float4 n2 = *(const float4*)(nrow + 8);
        float4 n3 = *(const float4*)(nrow + 12);
        float4 e0 = *(const float4*)(erow);
        float4 e1 = *(const float4*)(erow + 4);
        float4 e2 = *(const float4*)(erow + 8);
        float4 e3 = *(const float4*)(erow + 12);
        uint4 S0, S1, E0, E1;
        S0 = make_uint4(pack_h2(sgnf(n0.x), sgnf(n0.y)), pack_h2(sgnf(n0.z), sgnf(n0.w)),
                        pack_h2(sgnf(n1.x), sgnf(n1.y)), pack_h2(sgnf(n1.z), sgnf(n1.w)));
        S1 = make_uint4(pack_h2(sgnf(n2.x), sgnf(n2.y)), pack_h2(sgnf(n2.z), sgnf(n2.w)),
                        pack_h2(sgnf(n3.x), sgnf(n3.y)), pack_h2(sgnf(n3.z), sgnf(n3.w)));
        E0 = make_uint4(pack_h2(e0.x, e0.y), pack_h2(e0.z, e0.w),
                        pack_h2(e1.x, e1.y), pack_h2(e1.z, e1.w));
        E1 = make_uint4(pack_h2(e2.x, e2.y), pack_h2(e2.z, e2.w),
                        pack_h2(e3.x, e3.y), pack_h2(e3.z, e3.w));
        *(uint4*)(smem + 0 * A_BYTES + csts0) = S0;
        *(uint4*)(smem + 0 * A_BYTES + csts1) = S1;
        *(uint4*)(smem + 1 * A_BYTES + csts0) = E0;
        *(uint4*)(smem + 1 * A_BYTES + csts1) = E1;
    }
    CP_WAIT0();
    __syncthreads();

    float4 nv[4], ev[4];

#pragma unroll 1
    for (int s = 0; s < KSTAGES; ++s) {
        const uint32_t cur = (uint32_t)(s & 1) * STAGE_BYTES;
        const uint32_t nxt = (uint32_t)((s + 1) & 1) * STAGE_BYTES;

        // (a) prefetch stage s+1: B via cp.async, adjacency via LDG regs
        if (s + 1 < KSTAGES) {
            if (tid < 256) {
                const uint32_t dst = sb + nxt + ST_A2 + tid * 64;
                const char* src = fB + (size_t)(s + 1) * B_BYTES + tid * 64;
#pragma unroll
                for (int q = 0; q < 4; ++q) CP_ASYNC16(dst + q * 16, src + q * 16);
            }
            CP_COMMIT();
            const size_t k0 = (size_t)(s + 1) * BK;
#pragma unroll
            for (int i = 0; i < 4; ++i) {
                nv[i] = *(const float4*)(nrow + k0 + i * 4);
                ev[i] = *(const float4*)(erow + k0 + i * 4);
            }
        }

        // (b) compute stage s
        const uint32_t sbA = sb + cur;
        const uint32_t sbB = sb + cur + ST_A2;
#pragma unroll
        for (int ks = 0; ks < 4; ++ks) {
            uint32_t b[4][4];
#pragma unroll
            for (int np = 0; np < 4; ++np)
                LDSM_X4(b[np][0], b[np][1], b[np][2], b[np][3],
                        sbB + ((bbase[np] + ks * 32) ^ bxor[np]));
#pragma unroll
            for (int p = 0; p < 2; ++p) {
                uint32_t a[4];
                LDSM_X4(a[0], a[1], a[2], a[3],
                        sbA + p * A_BYTES + ((abase + ks * 32) ^ axor));
#pragma unroll
                for (int np = 0; np < 4; ++np) {
                    mma_f16(acc[p][np * 2],     a, b[np][0], b[np][1]);
                    mma_f16(acc[p][np * 2 + 1], a, b[np][2], b[np][3]);
                }
            }
        }

        // (c) convert + store stage s+1 A tiles; drain B copy; barrier
        if (s + 1 < KSTAGES) {
            char* bp = smem + ((s + 1) & 1) * STAGE_BYTES;
            uint4 S0, S1, E0, E1;
            S0 = make_uint4(pack_h2(sgnf(nv[0].x), sgnf(nv[0].y)), pack_h2(sgnf(nv[0].z), sgnf(nv[0].w)),
                            pack_h2(sgnf(nv[1].x), sgnf(nv[1].y)), pack_h2(sgnf(nv[1].z), sgnf(nv[1].w)));
            S1 = make_uint4(pack_h2(sgnf(nv[2].x), sgnf(nv[2].y)), pack_h2(sgnf(nv[2].z), sgnf(nv[2].w)),
                            pack_h2(sgnf(nv[3].x), sgnf(nv[3].y)), pack_h2(sgnf(nv[3].z), sgnf(nv[3].w)));
            E0 = make_uint4(pack_h2(ev[0].x, ev[0].y), pack_h2(ev[0].z, ev[0].w),
                            pack_h2(ev[1].x, ev[1].y), pack_h2(ev[1].z, ev[1].w));
            E1 = make_uint4(pack_h2(ev[2].x, ev[2].y), pack_h2(ev[2].z, ev[2].w),
                            pack_h2(ev[3].x, ev[3].y), pack_h2(ev[3].z, ev[3].w));
            *(uint4*)(bp + 0 * A_BYTES + csts0) = S0;
            *(uint4*)(bp + 0 * A_BYTES + csts1) = S1;
            *(uint4*)(bp + 1 * A_BYTES + csts0) = E0;
            *(uint4*)(bp + 1 * A_BYTES + csts1) = E1;
            CP_WAIT0();
            __syncthreads();
        }
    }

    // ---- epilogue: write partial planes for this k-slice ----
    const int er0 = wm + (lane >> 2);
    const int ec0 = wn + (lane & 3) * 2;
#pragma unroll
    for (int p = 0; p < 2; ++p) {
        float* base = g_S + (size_t)kslice * SLICE + (size_t)p * PLANE
                    + (size_t)(M0 + er0) * F + ec0;
#pragma unroll
        for (int nt = 0; nt < 8; ++nt) {
            *(float2*)(base + nt * 8)         = make_float2(acc[p][nt][0], acc[p][nt][1]);
            *(float2*)(base + 8 * F + nt * 8) = make_float2(acc[p][nt][2], acc[p][nt][3]);
        }
    }
}

// ---------------------------------------------------------------------------
// Combine: out = relu(sum_k Ssign_k @ Wd + b2) + sum_k Sedge_k @ We + eb
// ---------------------------------------------------------------------------
__device__ __forceinline__ void accum_block(const float* __restrict__ W,
                                            const float* __restrict__ S,
                                            float* acc,
                                            float* Ws, float* Ss,
                                            int tid, int tx, int ty, int R0) {
#pragma unroll 1
    for (int k0 = 0; k0 < 128; k0 += 32) {
        __syncthreads();
#pragma unroll
        for (int i = 0; i < 4; ++i) {
            const int e = tid + i * 256;
            const int wrow = e >> 5;
            const int wc = (e & 31) * 4;
            *(float4*)(Ws + wrow * 128 + wc) = *(const float4*)(W + (k0 + wrow) * 128 + wc);
        }
        {
            const int srow = tid >> 3;
            const int sc = (tid & 7) * 4;
            const size_t gi = (size_t)(R0 + srow) * F + k0 + sc;
            float4 t = *(const float4*)(S + gi);
#pragma unroll
            for (int sl = 1; sl < KSPLIT; ++sl) {
                float4 a = *(const float4*)(S + (size_t)sl * SLICE + gi);
                t.x += a.x; t.y += a.y; t.z += a.z; t.w += a.w;
            }
            *(float4*)(Ss + srow * 36 + sc) = t;
        }
        __syncthreads();
#pragma unroll 8
        for (int kk = 0; kk < 32; ++kk) {
            float w[4], sv[4];
#pragma unroll
            for (int v = 0; v < 4; ++v) w[v] = Ws[kk * 128 + tx + 32 * v];
#pragma unroll
            for (int u = 0; u < 4; ++u) sv[u] = Ss[(ty + 8 * u) * 36 + kk];
#pragma unroll
            for (int u = 0; u < 4; ++u)
#pragma unroll
                for (int v = 0; v < 4; ++v)
                    acc[u * 4 + v] = fmaf(sv[u], w[v], acc[u * 4 + v]);
        }
    }
}

__global__ __launch_bounds__(256)
void combine_kernel(const float* __restrict__ edge_weight,
                    const float* __restrict__ edge_bias,
                    float* __restrict__ out) {
    __shared__ float Ws[32 * 128];
    __shared__ float Ss[32 * 36];

    const int tid = threadIdx.x;
    const int tx = tid & 31;
    const int ty = tid >> 5;
    const int R0 = blockIdx.x * 32;

    float accN[16], accE[16];
#pragma unroll
    for (int i = 0; i < 16; ++i) { accN[i] = 0.f; accE[i] = 0.f; }

    accum_block(g_Wd,        g_S,         accN, Ws, Ss, tid, tx, ty, R0);  // sign planes
    accum_block(edge_weight, g_S + PLANE, accE, Ws, Ss, tid, tx, ty, R0);  // edge planes

    float b2[4], eb[4];
#pragma unroll
    for (int v = 0; v < 4; ++v) {
        b2[v] = g_b2[tx + 32 * v];
        eb[v] = edge_bias[tx + 32 * v];
    }
#pragma unroll
    for (int u = 0; u < 4; ++u)
#pragma unroll
        for (int v = 0; v < 4; ++v) {
            const int rr = R0 + ty + 8 * u;
            const int c = tx + 32 * v;
            out[(size_t)rr * F + c] =
                fmaxf(accN[u * 4 + v] + b2[v], 0.f) + accE[u * 4 + v] + eb[v];
        }
}

extern "C" void kernel_launch(void* const* d_in, const int* in_sizes, int n_in,
                              void* d_out, int out_size) {
    const float* feats       = (const float*)d_in[0];
    const float* node_adj    = (const float*)d_in[1];
    const float* edge_adj    = (const float*)d_in[2];
    const float* node_weight = (const float*)d_in[3];
    const float* node_bias   = (const float*)d_in[4];
    const float* edge_weight = (const float*)d_in[5];
    const float* edge_bias   = (const float*)d_in[6];
    float* out = (float*)d_out;

    cudaFuncSetAttribute(spmm2_f16, cudaFuncAttributeMaxDynamicSharedMemorySize, SMEM_TOTAL);

    zero_c_kernel<<<1, 128>>>();
    colsum_kernel<<<96, 128>>>(feats);
    wtrans_kernel<<<1, 128>>>(node_weight, node_bias);
    prep_feats<<<N_NODES / BK, 256>>>(feats);
    spmm2_f16<<<GRID, THREADS, SMEM_TOTAL>>>(node_adj, edge_adj);
    combine_kernel<<<N_NODES / 32, 256>>>(edge_weight, edge_bias, out);
}